// round 8
// baseline (speedup 1.0000x reference)
#include <cuda_runtime.h>
#include <cstdint>

#define HH 50
#define DD 64
#define NT 256

__global__ void zero_tail_kernel(float* __restrict__ out, int off) {
    if (threadIdx.x == 0) { out[off] = 0.f; out[off + 1] = 0.f; }
}

__global__ void __launch_bounds__(NT) fused_kernel(
    const int* __restrict__ user1, const int* __restrict__ item1,
    const int* __restrict__ user2, const int* __restrict__ item2,
    const int* __restrict__ u_his, const int* __restrict__ u_pos, const int* __restrict__ u_mask,
    const int* __restrict__ i_his, const int* __restrict__ i_pos, const int* __restrict__ i_mask,
    const float* __restrict__ user1_emb, const float* __restrict__ item1_emb,
    const float* __restrict__ user1_bias, const float* __restrict__ item1_bias,
    const float* __restrict__ u_pos_emb,
    const float* __restrict__ user2_emb, const float* __restrict__ item2_emb,
    const float* __restrict__ user2_bias, const float* __restrict__ item2_bias,
    const float* __restrict__ i_pos_emb,
    const float* __restrict__ attn_u_W, const float* __restrict__ attn_u_b,
    const float* __restrict__ attn_i_W, const float* __restrict__ attn_i_b,
    float* __restrict__ out, int B)
{
    __shared__ float kd[HH];
    __shared__ float swgt[2][HH];
    __shared__ __align__(16) float part[8][2][DD];   // per-warp partial d for 2 queries
    __shared__ float sred[8];

    const int tid   = threadIdx.x;
    const int b     = blockIdx.x;
    const int phase = blockIdx.y;            // 0 = u-branch keys, 1 = i-branch keys
    const int warp  = tid >> 5, lane = tid & 31;
    const int g     = tid >> 4, l16  = tid & 15;   // 16 groups x 16 lanes

    const int u1 = user1[b], i1 = item1[b], u2 = user2[b], i2 = item2[b];

    const int*   his  = phase ? i_his  : u_his;
    const int*   pos  = phase ? i_pos  : u_pos;
    const int*   msk  = phase ? i_mask : u_mask;
    const float* emb  = phase ? user2_emb : item1_emb;
    const float* pemb = phase ? i_pos_emb : u_pos_emb;
    const float* W    = phase ? attn_i_W  : attn_u_W;
    const float  batt = phase ? attn_i_b[0] : attn_u_b[0];

    // rows owned by this thread: h = p*16 + g, p = 0..3 (p=3 only for g<2)
    const int nrow = (g < 2) ? 4 : 3;

    // ---- stage 1: load all indices, then all embedding vectors (max MLP) ----
    int   ih[4], ip[4];
    float mm[4];
    #pragma unroll
    for (int p = 0; p < 4; ++p) {
        const int h = p * 16 + g;
        if (p < nrow) {
            ih[p] = __ldg(his + b * HH + h);
            ip[p] = __ldg(pos + b * HH + h);
            mm[p] = (__ldg(msk + b * HH + h) != 0) ? 1.f : 0.f;
        }
    }
    float4 e4[4], p4[4];
    #pragma unroll
    for (int p = 0; p < 4; ++p) {
        if (p < nrow) {
            e4[p] = __ldg((const float4*)emb  + (size_t)ih[p] * 16 + l16);
            p4[p] = __ldg((const float4*)pemb + (size_t)ip[p] * 16 + l16);
        }
    }

    // ---- stage 2: build K in regs; fused key-dot + masked reg-norm ----
    float4 k4[4];
    float  regacc = 0.f;
    {
        const float4 wk = __ldg((const float4*)(W + DD) + l16);
        #pragma unroll
        for (int p = 0; p < 4; ++p) {
            if (p < nrow) {
                const int h = p * 16 + g;
                float m = mm[p];
                regacc += m * (e4[p].x * e4[p].x + e4[p].y * e4[p].y
                             + e4[p].z * e4[p].z + e4[p].w * e4[p].w);
                k4[p].x = (e4[p].x + p4[p].x) * m; k4[p].y = (e4[p].y + p4[p].y) * m;
                k4[p].z = (e4[p].z + p4[p].z) * m; k4[p].w = (e4[p].w + p4[p].w) * m;
                float prt = k4[p].x * wk.x + k4[p].y * wk.y
                          + k4[p].z * wk.z + k4[p].w * wk.w;
                #pragma unroll
                for (int o = 8; o; o >>= 1) prt += __shfl_down_sync(0xffffffffu, prt, o, 16);
                if (l16 == 0) kd[h] = prt;
            } else {
                k4[p] = make_float4(0.f, 0.f, 0.f, 0.f);
            }
        }
    }
    __syncthreads();

    // ---- softmax weights for the 2 queries (warps 0,1) ----
    if (warp < 2) {
        const float* Q = phase
            ? (warp ? user1_emb + (size_t)u1 * DD : user2_emb + (size_t)u1 * DD)
            : (warp ? item2_emb + (size_t)i1 * DD : item1_emb + (size_t)i1 * DD);
        float q0 = __ldg(Q + lane), q1 = __ldg(Q + lane + 32);
        float cq = q0 * __ldg(W + lane) + q1 * __ldg(W + lane + 32);
        #pragma unroll
        for (int o = 16; o; o >>= 1) cq += __shfl_xor_sync(0xffffffffu, cq, o);
        cq += batt;

        float s0 = tanhf(cq + kd[lane]);
        float s1 = (lane + 32 < HH) ? tanhf(cq + kd[lane + 32]) : -1e30f;
        float mx = fmaxf(s0, s1);
        #pragma unroll
        for (int o = 16; o; o >>= 1) mx = fmaxf(mx, __shfl_xor_sync(0xffffffffu, mx, o));
        float e0 = __expf(s0 - mx);
        float e1 = (lane + 32 < HH) ? __expf(s1 - mx) : 0.f;
        float se = e0 + e1;
        #pragma unroll
        for (int o = 16; o; o >>= 1) se += __shfl_xor_sync(0xffffffffu, se, o);
        float inv = 1.f / se;
        swgt[warp][lane] = e0 * inv;
        if (lane + 32 < HH) swgt[warp][lane + 32] = e1 * inv;
    }
    __syncthreads();

    // ---- weighted sum in registers; cross-group reduce ----
    {
        float4 aA = make_float4(0.f, 0.f, 0.f, 0.f);
        float4 aB = make_float4(0.f, 0.f, 0.f, 0.f);
        #pragma unroll
        for (int p = 0; p < 4; ++p) {
            const int h = p * 16 + g;
            if (p < nrow) {
                float wA = swgt[0][h], wB = swgt[1][h];
                aA.x += wA * k4[p].x; aA.y += wA * k4[p].y;
                aA.z += wA * k4[p].z; aA.w += wA * k4[p].w;
                aB.x += wB * k4[p].x; aB.y += wB * k4[p].y;
                aB.z += wB * k4[p].z; aB.w += wB * k4[p].w;
            }
        }
        // combine the two 16-lane groups within each warp
        aA.x += __shfl_down_sync(0xffffffffu, aA.x, 16);
        aA.y += __shfl_down_sync(0xffffffffu, aA.y, 16);
        aA.z += __shfl_down_sync(0xffffffffu, aA.z, 16);
        aA.w += __shfl_down_sync(0xffffffffu, aA.w, 16);
        aB.x += __shfl_down_sync(0xffffffffu, aB.x, 16);
        aB.y += __shfl_down_sync(0xffffffffu, aB.y, 16);
        aB.z += __shfl_down_sync(0xffffffffu, aB.z, 16);
        aB.w += __shfl_down_sync(0xffffffffu, aB.w, 16);
        if (lane < 16) {
            ((float4*)part[warp][0])[l16] = aA;
            ((float4*)part[warp][1])[l16] = aB;
        }
    }
    __syncthreads();

    // ---- fold 8 warp-partials, final logits (warps 0,1) + reg-loss norms ----
    if (warp < 2) {
        const int q = warp;
        float d0 = 0.f, d1 = 0.f;
        #pragma unroll
        for (int w = 0; w < 8; ++w) {
            float2 t = *(const float2*)&part[w][q][2 * lane];
            d0 += t.x; d1 += t.y;
        }

        const float *Av, *Bv; float bias; int ooff;
        if (phase == 0) {
            if (q == 0) {      // logits_us
                Av = item1_emb + (size_t)i1 * DD; Bv = user1_emb + (size_t)u1 * DD;
                bias = user1_bias[u1] + item1_bias[i1]; ooff = b;
            } else {           // logits_ur
                Av = item1_emb + (size_t)i2 * DD; Bv = user1_emb + (size_t)u2 * DD;
                bias = user1_bias[u2] + item1_bias[i2]; ooff = 2 * B + b;
            }
        } else {
            if (q == 0) {      // logits_ir
                Av = item2_emb + (size_t)i1 * DD; Bv = user2_emb + (size_t)u1 * DD;
                bias = user2_bias[u1] + item2_bias[i1]; ooff = B + b;
            } else {           // logits_is
                Av = item2_emb + (size_t)i2 * DD; Bv = user2_emb + (size_t)u2 * DD;
                bias = user2_bias[u2] + item2_bias[i2]; ooff = 3 * B + b;
            }
        }
        float2 av = __ldg((const float2*)Av + lane);
        float2 bv = __ldg((const float2*)Bv + lane);
        float lg = (d0 + av.x) * bv.x + (d1 + av.y) * bv.y;
        #pragma unroll
        for (int o = 16; o; o >>= 1) lg += __shfl_xor_sync(0xffffffffu, lg, o);
        if (lane == 0) out[ooff] = lg + bias;

        // reg1 += ||u1s||^2+||i1s||^2 (phase0,q0) ; reg2 += ||u2s||^2+||i2s||^2 (phase1,q1)
        if ((phase == 0 && q == 0) || (phase == 1 && q == 1))
            regacc += av.x * av.x + av.y * av.y + bv.x * bv.x + bv.y * bv.y;
    }

    // ---- block reduce reg loss, one atomic per block into out[4B + phase] ----
    #pragma unroll
    for (int o = 16; o; o >>= 1) regacc += __shfl_xor_sync(0xffffffffu, regacc, o);
    if (lane == 0) sred[warp] = regacc;
    __syncthreads();
    if (tid == 0) {
        float s = sred[0] + sred[1] + sred[2] + sred[3]
                + sred[4] + sred[5] + sred[6] + sred[7];
        atomicAdd(out + 4 * B + phase, s);
    }
}

extern "C" void kernel_launch(void* const* d_in, const int* in_sizes, int n_in,
                              void* d_out, int out_size) {
    const int B = in_sizes[0];
    float* out = (float*)d_out;

    zero_tail_kernel<<<1, 32>>>(out, 4 * B);
    fused_kernel<<<dim3(B, 2), NT>>>(
        (const int*)d_in[0], (const int*)d_in[1], (const int*)d_in[2], (const int*)d_in[3],
        (const int*)d_in[4], (const int*)d_in[5], (const int*)d_in[6],
        (const int*)d_in[7], (const int*)d_in[8], (const int*)d_in[9],
        (const float*)d_in[10], (const float*)d_in[11],
        (const float*)d_in[12], (const float*)d_in[13],
        (const float*)d_in[14],
        (const float*)d_in[15], (const float*)d_in[16],
        (const float*)d_in[17], (const float*)d_in[18],
        (const float*)d_in[19],
        (const float*)d_in[20], (const float*)d_in[21],
        (const float*)d_in[22], (const float*)d_in[23],
        out, B);
}

// round 9
// speedup vs baseline: 1.3226x; 1.3226x over previous
#include <cuda_runtime.h>
#include <cstdint>

#define HH 50
#define DD 64
#define NT 128

__global__ void zero_tail_kernel(float* __restrict__ out, int off) {
    if (threadIdx.x == 0) { out[off] = 0.f; out[off + 1] = 0.f; }
}

__global__ void __launch_bounds__(NT) fused_kernel(
    const int* __restrict__ user1, const int* __restrict__ item1,
    const int* __restrict__ user2, const int* __restrict__ item2,
    const int* __restrict__ u_his, const int* __restrict__ u_pos, const int* __restrict__ u_mask,
    const int* __restrict__ i_his, const int* __restrict__ i_pos, const int* __restrict__ i_mask,
    const float* __restrict__ user1_emb, const float* __restrict__ item1_emb,
    const float* __restrict__ user1_bias, const float* __restrict__ item1_bias,
    const float* __restrict__ u_pos_emb,
    const float* __restrict__ user2_emb, const float* __restrict__ item2_emb,
    const float* __restrict__ user2_bias, const float* __restrict__ item2_bias,
    const float* __restrict__ i_pos_emb,
    const float* __restrict__ attn_u_W, const float* __restrict__ attn_u_b,
    const float* __restrict__ attn_i_W, const float* __restrict__ attn_i_b,
    float* __restrict__ out, int B)
{
    __shared__ float kd[HH];
    __shared__ float swgt[2][HH];
    __shared__ __align__(16) float part[4][2][DD];   // per-warp partial d for 2 queries
    __shared__ __align__(16) float sAv[2][DD], sBv[2][DD];  // final-logit vectors (by warps 2,3)
    __shared__ float sred[4];

    const int tid   = threadIdx.x;
    const int b     = blockIdx.x;
    const int phase = blockIdx.y;            // 0 = u-branch keys, 1 = i-branch keys
    const int warp  = tid >> 5, lane = tid & 31;
    const int g     = tid >> 4, l16  = tid & 15;

    const int u1 = user1[b], i1 = item1[b], u2 = user2[b], i2 = item2[b];

    const int*   his  = phase ? i_his  : u_his;
    const int*   pos  = phase ? i_pos  : u_pos;
    const int*   msk  = phase ? i_mask : u_mask;
    const float* emb  = phase ? user2_emb : item1_emb;
    const float* pemb = phase ? i_pos_emb : u_pos_emb;
    const float* W    = phase ? attn_i_W  : attn_u_W;
    const float  batt = phase ? attn_i_b[0] : attn_u_b[0];

    // ---- prefetch Q for softmax (warps 0,1) — overlaps the gather below ----
    float q0 = 0.f, q1 = 0.f;
    if (warp < 2) {
        const float* Q = phase
            ? (warp ? user1_emb + (size_t)u1 * DD : user2_emb + (size_t)u1 * DD)
            : (warp ? item2_emb + (size_t)i1 * DD : item1_emb + (size_t)i1 * DD);
        q0 = __ldg(Q + lane); q1 = __ldg(Q + lane + 32);
    }

    // ---- gather: K stays in registers (7 float4/thread); fused key-dot + reg-norm ----
    float4 k4[7];
    float  regacc = 0.f;
    {
        const float4 wk = __ldg((const float4*)(W + DD) + l16);
        #pragma unroll
        for (int p = 0; p < 7; ++p) {
            const int h = p * 8 + g;
            if (h < HH) {
                int   ih = __ldg(his + b * HH + h);
                int   ip = __ldg(pos + b * HH + h);
                float m  = (__ldg(msk + b * HH + h) != 0) ? 1.f : 0.f;
                float4 e  = __ldg((const float4*)emb  + (size_t)ih * 16 + l16);
                float4 pp = __ldg((const float4*)pemb + (size_t)ip * 16 + l16);
                regacc += m * (e.x * e.x + e.y * e.y + e.z * e.z + e.w * e.w);
                k4[p].x = (e.x + pp.x) * m; k4[p].y = (e.y + pp.y) * m;
                k4[p].z = (e.z + pp.z) * m; k4[p].w = (e.w + pp.w) * m;
                float prt = k4[p].x * wk.x + k4[p].y * wk.y
                          + k4[p].z * wk.z + k4[p].w * wk.w;
                #pragma unroll
                for (int o = 8; o; o >>= 1) prt += __shfl_down_sync(0xffffffffu, prt, o, 16);
                if (l16 == 0) kd[h] = prt;
            } else {
                k4[p] = make_float4(0.f, 0.f, 0.f, 0.f);
            }
        }
    }
    __syncthreads();

    // ---- concurrent: warps 0,1 softmax | warps 2,3 stage Av/Bv into smem ----
    if (warp < 2) {
        float cq = q0 * __ldg(W + lane) + q1 * __ldg(W + lane + 32);
        #pragma unroll
        for (int o = 16; o; o >>= 1) cq += __shfl_xor_sync(0xffffffffu, cq, o);
        cq += batt;

        // scores = tanh(..) in [-1,1] -> exp is safe without max subtraction
        float e0 = __expf(tanhf(cq + kd[lane]));
        float e1 = (lane + 32 < HH) ? __expf(tanhf(cq + kd[lane + 32])) : 0.f;
        float se = e0 + e1;
        #pragma unroll
        for (int o = 16; o; o >>= 1) se += __shfl_xor_sync(0xffffffffu, se, o);
        float inv = 1.f / se;
        swgt[warp][lane] = e0 * inv;
        if (lane + 32 < HH) swgt[warp][lane + 32] = e1 * inv;
    } else {
        const int q = warp - 2;   // warp2 -> query 0, warp3 -> query 1
        const float *Av, *Bv;
        if (phase == 0) {
            if (q == 0) { Av = item1_emb + (size_t)i1 * DD; Bv = user1_emb + (size_t)u1 * DD; }
            else        { Av = item1_emb + (size_t)i2 * DD; Bv = user1_emb + (size_t)u2 * DD; }
        } else {
            if (q == 0) { Av = item2_emb + (size_t)i1 * DD; Bv = user2_emb + (size_t)u1 * DD; }
            else        { Av = item2_emb + (size_t)i2 * DD; Bv = user2_emb + (size_t)u2 * DD; }
        }
        float2 av = __ldg((const float2*)Av + lane);
        float2 bv = __ldg((const float2*)Bv + lane);
        ((float2*)sAv[q])[lane] = av;
        ((float2*)sBv[q])[lane] = bv;
    }
    __syncthreads();

    // ---- weighted sum fully in registers; cheap cross-group reduce ----
    {
        float4 aA = make_float4(0.f, 0.f, 0.f, 0.f);
        float4 aB = make_float4(0.f, 0.f, 0.f, 0.f);
        #pragma unroll
        for (int p = 0; p < 7; ++p) {
            const int h = p * 8 + g;
            if (h < HH) {
                float wA = swgt[0][h], wB = swgt[1][h];
                aA.x += wA * k4[p].x; aA.y += wA * k4[p].y;
                aA.z += wA * k4[p].z; aA.w += wA * k4[p].w;
                aB.x += wB * k4[p].x; aB.y += wB * k4[p].y;
                aB.z += wB * k4[p].z; aB.w += wB * k4[p].w;
            }
        }
        aA.x += __shfl_down_sync(0xffffffffu, aA.x, 16);
        aA.y += __shfl_down_sync(0xffffffffu, aA.y, 16);
        aA.z += __shfl_down_sync(0xffffffffu, aA.z, 16);
        aA.w += __shfl_down_sync(0xffffffffu, aA.w, 16);
        aB.x += __shfl_down_sync(0xffffffffu, aB.x, 16);
        aB.y += __shfl_down_sync(0xffffffffu, aB.y, 16);
        aB.z += __shfl_down_sync(0xffffffffu, aB.z, 16);
        aB.w += __shfl_down_sync(0xffffffffu, aB.w, 16);
        if (lane < 16) {
            ((float4*)part[warp][0])[l16] = aA;
            ((float4*)part[warp][1])[l16] = aB;
        }
    }
    __syncthreads();

    // ---- fold 4 warp-partials, final logits (warps 0,1) + reg-loss vector norms ----
    if (warp < 2) {
        const int q = warp;
        float d0 = 0.f, d1 = 0.f;
        #pragma unroll
        for (int w = 0; w < 4; ++w) {
            float2 t = *(const float2*)&part[w][q][2 * lane];
            d0 += t.x; d1 += t.y;
        }

        float bias; int ooff;
        if (phase == 0) {
            if (q == 0) { bias = user1_bias[u1] + item1_bias[i1]; ooff = b; }
            else        { bias = user1_bias[u2] + item1_bias[i2]; ooff = 2 * B + b; }
        } else {
            if (q == 0) { bias = user2_bias[u1] + item2_bias[i1]; ooff = B + b; }
            else        { bias = user2_bias[u2] + item2_bias[i2]; ooff = 3 * B + b; }
        }
        float2 av = ((const float2*)sAv[q])[lane];
        float2 bv = ((const float2*)sBv[q])[lane];
        float lg = (d0 + av.x) * bv.x + (d1 + av.y) * bv.y;
        #pragma unroll
        for (int o = 16; o; o >>= 1) lg += __shfl_xor_sync(0xffffffffu, lg, o);
        if (lane == 0) out[ooff] = lg + bias;

        // reg1 += ||u1s||^2+||i1s||^2 (phase0,q0) ; reg2 += ||u2s||^2+||i2s||^2 (phase1,q1)
        if ((phase == 0 && q == 0) || (phase == 1 && q == 1))
            regacc += av.x * av.x + av.y * av.y + bv.x * bv.x + bv.y * bv.y;
    }

    // ---- block reduce reg loss, one atomic per block into out[4B + phase] ----
    #pragma unroll
    for (int o = 16; o; o >>= 1) regacc += __shfl_xor_sync(0xffffffffu, regacc, o);
    if (lane == 0) sred[warp] = regacc;
    __syncthreads();
    if (tid == 0)
        atomicAdd(out + 4 * B + phase, sred[0] + sred[1] + sred[2] + sred[3]);
}

extern "C" void kernel_launch(void* const* d_in, const int* in_sizes, int n_in,
                              void* d_out, int out_size) {
    const int B = in_sizes[0];
    float* out = (float*)d_out;

    zero_tail_kernel<<<1, 32>>>(out, 4 * B);
    fused_kernel<<<dim3(B, 2), NT>>>(
        (const int*)d_in[0], (const int*)d_in[1], (const int*)d_in[2], (const int*)d_in[3],
        (const int*)d_in[4], (const int*)d_in[5], (const int*)d_in[6],
        (const int*)d_in[7], (const int*)d_in[8], (const int*)d_in[9],
        (const float*)d_in[10], (const float*)d_in[11],
        (const float*)d_in[12], (const float*)d_in[13],
        (const float*)d_in[14],
        (const float*)d_in[15], (const float*)d_in[16],
        (const float*)d_in[17], (const float*)d_in[18],
        (const float*)d_in[19],
        (const float*)d_in[20], (const float*)d_in[21],
        (const float*)d_in[22], (const float*)d_in[23],
        out, B);
}